// round 1
// baseline (speedup 1.0000x reference)
#include <cuda_runtime.h>
#include <math.h>
#include <stdint.h>

// ---------------- problem constants ----------------
// B=1024, ENC=1024, S=3, D=256, B*S=3072, S*D=768
static constexpr int Bn   = 1024;
static constexpr int ENC  = 1024;
static constexpr int M3   = 3072;   // B*S
static constexpr int Dd   = 256;
static constexpr int SD   = 768;
static constexpr int OUT1 = 512;
static constexpr int LAT  = 128;

static constexpr size_t N_BE  = (size_t)Bn * ENC;   // 1048576
static constexpr size_t N_BSD = (size_t)M3 * Dd;    // 786432

// scratch: vis, aud + 20 [3072,256] buffers + h1[1024,512]
__device__ float g_scratch[2 * N_BE + 20 * N_BSD + (size_t)Bn * OUT1];

__device__ __forceinline__ float sigm(float x) { return 1.0f / (1.0f + expf(-x)); }

// ---------------- generic fp32 GEMM: C = [relu]( A[M,K] @ W[N,K]^T + bias[N] ) ----------------
// flags: bit0 = relu, bit1 = accumulate into C (C += result+bias)
#define BM 64
#define BN 64
#define BK 16

__global__ void __launch_bounds__(256) gemm_kernel(
    const float* __restrict__ A, const float* __restrict__ W,
    const float* __restrict__ bias, float* __restrict__ C,
    int M, int N, int K, int flags)
{
    __shared__ __align__(16) float As[BK][BM + 4];
    __shared__ __align__(16) float Ws[BK][BN + 4];
    const int tid = threadIdx.x;
    const int tx = tid & 15, ty = tid >> 4;
    const int m0 = blockIdx.y * BM, n0 = blockIdx.x * BN;
    const int lm = tid >> 2;          // 0..63
    const int lk = (tid & 3) << 2;    // 0,4,8,12
    const float* Ag = A + (size_t)(m0 + lm) * K + lk;
    const float* Wg = W + (size_t)(n0 + lm) * K + lk;

    float acc[4][4] = {};
    for (int kt = 0; kt < K; kt += BK) {
        float4 av = *(const float4*)(Ag + kt);
        float4 wv = *(const float4*)(Wg + kt);
        As[lk + 0][lm] = av.x; As[lk + 1][lm] = av.y;
        As[lk + 2][lm] = av.z; As[lk + 3][lm] = av.w;
        Ws[lk + 0][lm] = wv.x; Ws[lk + 1][lm] = wv.y;
        Ws[lk + 2][lm] = wv.z; Ws[lk + 3][lm] = wv.w;
        __syncthreads();
#pragma unroll
        for (int k = 0; k < BK; k++) {
            float4 a = *(const float4*)&As[k][ty << 2];
            float4 b = *(const float4*)&Ws[k][tx << 2];
            acc[0][0] = fmaf(a.x, b.x, acc[0][0]); acc[0][1] = fmaf(a.x, b.y, acc[0][1]);
            acc[0][2] = fmaf(a.x, b.z, acc[0][2]); acc[0][3] = fmaf(a.x, b.w, acc[0][3]);
            acc[1][0] = fmaf(a.y, b.x, acc[1][0]); acc[1][1] = fmaf(a.y, b.y, acc[1][1]);
            acc[1][2] = fmaf(a.y, b.z, acc[1][2]); acc[1][3] = fmaf(a.y, b.w, acc[1][3]);
            acc[2][0] = fmaf(a.z, b.x, acc[2][0]); acc[2][1] = fmaf(a.z, b.y, acc[2][1]);
            acc[2][2] = fmaf(a.z, b.z, acc[2][2]); acc[2][3] = fmaf(a.z, b.w, acc[2][3]);
            acc[3][0] = fmaf(a.w, b.x, acc[3][0]); acc[3][1] = fmaf(a.w, b.y, acc[3][1]);
            acc[3][2] = fmaf(a.w, b.z, acc[3][2]); acc[3][3] = fmaf(a.w, b.w, acc[3][3]);
        }
        __syncthreads();
    }
#pragma unroll
    for (int i = 0; i < 4; i++) {
#pragma unroll
        for (int j = 0; j < 4; j++) {
            int row = m0 + (ty << 2) + i;
            int col = n0 + (tx << 2) + j;
            float v = acc[i][j] + bias[col];
            if (flags & 1) v = fmaxf(v, 0.0f);
            size_t idx = (size_t)row * N + col;
            if (flags & 2) C[idx] += v; else C[idx] = v;
        }
    }
}

// ---------------- attention kernel: all 4 tiny (3x3) attentions per batch ----------------
__global__ void __launch_bounds__(256) attn_kernel(
    const float* __restrict__ xv, const float* __restrict__ xa,
    const float* __restrict__ qv, const float* __restrict__ qa,
    const float* __restrict__ kv, const float* __restrict__ ka,
    float* __restrict__ ava, float* __restrict__ av_,
    float* __restrict__ aav, float* __restrict__ aa_)
{
    __shared__ float s_x[2][3][256];
    __shared__ float s_q[2][3][256];
    __shared__ float s_k[2][3][256];
    __shared__ float s_sc[4][3][3];
    const int tid = threadIdx.x;
    const size_t base = (size_t)blockIdx.x * 768;

    float* fx = &s_x[0][0][0];
    float* fq = &s_q[0][0][0];
    float* fk = &s_k[0][0][0];
    for (int idx = tid; idx < 768; idx += 256) {
        fx[idx] = xv[base + idx]; fx[768 + idx] = xa[base + idx];
        fq[idx] = qv[base + idx]; fq[768 + idx] = qa[base + idx];
        fk[idx] = kv[base + idx]; fk[768 + idx] = ka[base + idx];
    }
    __syncthreads();

    const int w = tid >> 5, lane = tid & 31;
    // type 0: (q_v,k_a)->x_a ; 1: (q_v,k_v)->x_v ; 2: (q_a,k_v)->x_v ; 3: (q_a,k_a)->x_a
    for (int task = w; task < 36; task += 8) {
        int type = task / 9, rem = task % 9, s3 = rem / 3, t3 = rem % 3;
        int qsel = type >> 1;
        int ksel = (type == 0 || type == 3) ? 1 : 0;
        float sum = 0.0f;
        for (int d = lane; d < 256; d += 32) sum += s_q[qsel][s3][d] * s_k[ksel][t3][d];
#pragma unroll
        for (int off = 16; off; off >>= 1) sum += __shfl_down_sync(0xffffffffu, sum, off);
        if (lane == 0) s_sc[type][s3][t3] = sum;
    }
    __syncthreads();

    if (tid < 12) {
        int type = tid / 3, s3 = tid % 3;
        float a = s_sc[type][s3][0], b = s_sc[type][s3][1], c = s_sc[type][s3][2];
        float m = fmaxf(a, fmaxf(b, c));
        float ea = expf(a - m), eb = expf(b - m), ec = expf(c - m);
        float inv = 0.0625f / (ea + eb + ec);   // softmax, then *1/sqrt(256)
        s_sc[type][s3][0] = ea * inv; s_sc[type][s3][1] = eb * inv; s_sc[type][s3][2] = ec * inv;
    }
    __syncthreads();

    for (int idx = tid; idx < 3072; idx += 256) {
        int type = idx / 768, rem = idx % 768;
        int s3 = rem >> 8, d = rem & 255;
        int xsel = (type == 0 || type == 3) ? 1 : 0;
        float v = s_sc[type][s3][0] * s_x[xsel][0][d]
                + s_sc[type][s3][1] * s_x[xsel][1][d]
                + s_sc[type][s3][2] * s_x[xsel][2][d];
        float* outp = (type == 0) ? ava : (type == 1) ? av_ : (type == 2) ? aav : aa_;
        outp[base + rem] = v;
    }
}

// ---------------- bilinear: j[r,o] = sigmoid( c_va[r,:] · W[o] · c_av[r,:] ) ----------------
// One output channel o per blockIdx.y, 32 rows per blockIdx.x. 8 threads/row, each owns
// a 32-element j-slice of c_av in registers. W[o] streamed through smem in 8-row tiles.
static constexpr int BIL_ROWS = 32;
static constexpr int BIL_IB   = 8;

__global__ void __launch_bounds__(256) bilinear_kernel(
    const float* __restrict__ cva, const float* __restrict__ cav,
    const float* __restrict__ Wb, float* __restrict__ Jout)
{
    __shared__ float s_cva[BIL_ROWS][257];
    __shared__ __align__(16) float s_W[BIL_IB * 256];
    const int tid = threadIdx.x;
    const int o = blockIdx.y;
    const int r = tid >> 3;
    const int q = tid & 7;
    const int r0 = blockIdx.x * BIL_ROWS + r;

    for (int idx = tid; idx < BIL_ROWS * 256; idx += 256)
        s_cva[idx >> 8][idx & 255] =
            cva[(size_t)(blockIdx.x * BIL_ROWS + (idx >> 8)) * 256 + (idx & 255)];

    float4 ca[8];
#pragma unroll
    for (int jj = 0; jj < 8; jj++)
        ca[jj] = *(const float4*)(cav + (size_t)r0 * 256 + q * 4 + jj * 32);
    __syncthreads();

    const float* Wo = Wb + (size_t)o * 65536;
    float acc = 0.0f;
    for (int ib = 0; ib < 256 / BIL_IB; ib++) {
        const float4* wg = (const float4*)(Wo + (size_t)ib * BIL_IB * 256);
        float4* ws4 = (float4*)s_W;
        ws4[tid] = wg[tid];
        ws4[tid + 256] = wg[tid + 256];
        __syncthreads();
#pragma unroll
        for (int ii = 0; ii < BIL_IB; ii++) {
            float cv = s_cva[r][ib * BIL_IB + ii];
            const float4* wr = (const float4*)(s_W + ii * 256);
            float p0 = 0, p1 = 0, p2 = 0, p3 = 0;
#pragma unroll
            for (int jj = 0; jj < 8; jj++) {
                float4 wv = wr[q + jj * 8];     // word offset 4q + 32jj — matches ca[jj]
                p0 = fmaf(wv.x, ca[jj].x, p0);
                p1 = fmaf(wv.y, ca[jj].y, p1);
                p2 = fmaf(wv.z, ca[jj].z, p2);
                p3 = fmaf(wv.w, ca[jj].w, p3);
            }
            acc = fmaf(cv, (p0 + p1) + (p2 + p3), acc);
        }
        __syncthreads();
    }
    acc += __shfl_down_sync(0xffffffffu, acc, 4, 8);
    acc += __shfl_down_sync(0xffffffffu, acc, 2, 8);
    acc += __shfl_down_sync(0xffffffffu, acc, 1, 8);
    if (q == 0) Jout[(size_t)r0 * 256 + o] = sigm(acc);
}

// ---------------- elementwise kernels ----------------
__global__ void ew_sigmul_kernel(const float* __restrict__ L, const float* __restrict__ a,
                                 float* __restrict__ out, int n)
{
    int i = blockIdx.x * 256 + threadIdx.x;
    if (i < n) out[i] = sigm(L[i] * a[i]);
}

__global__ void ew_mul_kernel(const float* __restrict__ a, const float* __restrict__ b,
                              float* __restrict__ out, int n)
{
    int i = blockIdx.x * 256 + threadIdx.x;
    if (i < n) out[i] = a[i] * b[i];
}

__global__ void ew_combine_kernel(const float* __restrict__ j, const float* __restrict__ xv,
                                  const float* __restrict__ xa, const float* __restrict__ tcp,
                                  float* __restrict__ out, int n)
{
    int i = blockIdx.x * 256 + threadIdx.x;
    if (i < n) {
        float tc = *tcp;
        float jv = j[i];
        out[i] = tc * jv * xv[i] + (1.0f - jv) * xa[i];
    }
}

// ---------------- classifier: P = relu(F[1024,128]@W1[32,128]^T) @ W2[10,32]^T ----------------
__global__ void __launch_bounds__(256) cls_kernel(
    const float* __restrict__ F, const float* __restrict__ W1,
    const float* __restrict__ W2, float* __restrict__ P)
{
    __shared__ float s_f[8][128];
    __shared__ float s_w1[32][129];
    __shared__ float s_w2[320];
    __shared__ float s_h[8][32];
    const int tid = threadIdx.x;
    const int r0 = blockIdx.x * 8;
    for (int idx = tid; idx < 1024; idx += 256) s_f[idx >> 7][idx & 127] = F[(size_t)r0 * 128 + idx];
    for (int idx = tid; idx < 4096; idx += 256) s_w1[idx >> 7][idx & 127] = W1[idx];
    for (int idx = tid; idx < 320; idx += 256) s_w2[idx] = W2[idx];
    __syncthreads();
    const int w = tid >> 5, lane = tid & 31;
    float h = 0.0f;
#pragma unroll 8
    for (int d = 0; d < 128; d++) h = fmaf(s_f[w][d], s_w1[lane][d], h);
    s_h[w][lane] = fmaxf(h, 0.0f);
    __syncwarp();
    if (lane < 10) {
        float p = 0.0f;
#pragma unroll
        for (int k = 0; k < 32; k++) p = fmaf(s_h[w][k], s_w2[lane * 32 + k], p);
        P[(size_t)(r0 + w) * 10 + lane] = p;
    }
}

// ---------------- host ----------------
static void launch_gemm(const float* A, const float* W, const float* b, float* C,
                        int M, int N, int K, int flags)
{
    dim3 grid(N / BN, M / BM);
    gemm_kernel<<<grid, 256>>>(A, W, b, C, M, N, K, flags);
}

extern "C" void kernel_launch(void* const* d_in, const int* in_sizes, int n_in,
                              void* d_out, int out_size)
{
    const float* img    = (const float*)d_in[0];
    const float* audio  = (const float*)d_in[1];
    const float* vis_W  = (const float*)d_in[2];
    const float* vis_b  = (const float*)d_in[3];
    const float* aud_W  = (const float*)d_in[4];
    const float* aud_b  = (const float*)d_in[5];
    const float* msv_W  = (const float*)d_in[6];
    const float* msv_b  = (const float*)d_in[7];
    const float* msa_W  = (const float*)d_in[8];
    const float* msa_b  = (const float*)d_in[9];
    const float* mmfaW  = (const float*)d_in[10];
    const float* mmfaB  = (const float*)d_in[11];
    const float* bilW   = (const float*)d_in[12];
    const float* t_c    = (const float*)d_in[13];
    const float* out_W1 = (const float*)d_in[14];
    const float* out_b1 = (const float*)d_in[15];
    const float* out_W2 = (const float*)d_in[16];
    const float* out_b2 = (const float*)d_in[17];
    const float* clsvW1 = (const float*)d_in[18];
    const float* clsvW2 = (const float*)d_in[19];
    const float* clsaW1 = (const float*)d_in[20];
    const float* clsaW2 = (const float*)d_in[21];

    float* S = nullptr;
    cudaGetSymbolAddress((void**)&S, g_scratch);

    float* p_vis = S;
    float* p_aud = p_vis + N_BE;
    float* p_vms = p_aud + N_BE;
    float* p_ams = p_vms + N_BSD;
    float* p_xv  = p_ams + N_BSD;
    float* p_xa  = p_xv  + N_BSD;
    float* p_qv  = p_xa  + N_BSD;
    float* p_qa  = p_qv  + N_BSD;
    float* p_kv  = p_qa  + N_BSD;
    float* p_ka  = p_kv  + N_BSD;
    float* p_ava = p_ka  + N_BSD;
    float* p_av  = p_ava + N_BSD;
    float* p_aav = p_av  + N_BSD;
    float* p_aa  = p_aav + N_BSD;
    float* p_L45 = p_aa  + N_BSD;
    float* p_L67 = p_L45 + N_BSD;
    float* p_cva = p_L67 + N_BSD;
    float* p_cav = p_cva + N_BSD;
    float* p_j   = p_cav + N_BSD;
    float* p_m   = p_j   + N_BSD;
    float* p_ov  = p_m   + N_BSD;
    float* p_oa  = p_ov  + N_BSD;
    float* p_h   = p_oa  + N_BSD;

    const int nEW = (int)N_BSD;   // 786432

    auto run_mmfa = [&](const float* xv, const float* xa, float* outm) {
        launch_gemm(xv, mmfaW + 0 * 65536, mmfaB + 0 * 256, p_qv, M3, Dd, Dd, 0);
        launch_gemm(xa, mmfaW + 1 * 65536, mmfaB + 1 * 256, p_qa, M3, Dd, Dd, 0);
        launch_gemm(xv, mmfaW + 2 * 65536, mmfaB + 2 * 256, p_kv, M3, Dd, Dd, 0);
        launch_gemm(xa, mmfaW + 3 * 65536, mmfaB + 3 * 256, p_ka, M3, Dd, Dd, 0);
        attn_kernel<<<Bn, 256>>>(xv, xa, p_qv, p_qa, p_kv, p_ka, p_ava, p_av, p_aav, p_aa);
        launch_gemm(p_ava, mmfaW + 4 * 65536, mmfaB + 4 * 256, p_L45, M3, Dd, Dd, 0);
        launch_gemm(p_av,  mmfaW + 5 * 65536, mmfaB + 5 * 256, p_L45, M3, Dd, Dd, 2);
        launch_gemm(p_aav, mmfaW + 6 * 65536, mmfaB + 6 * 256, p_L67, M3, Dd, Dd, 0);
        launch_gemm(p_aa,  mmfaW + 7 * 65536, mmfaB + 7 * 256, p_L67, M3, Dd, Dd, 2);
        ew_sigmul_kernel<<<nEW / 256, 256>>>(p_L45, p_av, p_cva, nEW);
        ew_sigmul_kernel<<<nEW / 256, 256>>>(p_L67, p_aa, p_cav, nEW);
        dim3 bg(M3 / BIL_ROWS, 256);
        bilinear_kernel<<<bg, 256>>>(p_cva, p_cav, bilW, p_j);
        ew_combine_kernel<<<nEW / 256, 256>>>(p_j, xv, xa, t_c, outm, nEW);
    };

    // encoders + multi-scale
    launch_gemm(img,   vis_W, vis_b, p_vis, Bn, ENC, 4096, 1);
    launch_gemm(audio, aud_W, aud_b, p_aud, Bn, ENC, 1024, 1);
    launch_gemm(p_vis, msv_W, msv_b, p_vms, Bn, SD, ENC, 1);
    launch_gemm(p_aud, msa_W, msa_b, p_ams, Bn, SD, ENC, 1);

    // MMfa 1
    run_mmfa(p_vms, p_ams, p_m);
    ew_mul_kernel<<<nEW / 256, 256>>>(p_m, p_vms, p_xv, nEW);
    ew_mul_kernel<<<nEW / 256, 256>>>(p_m, p_ams, p_xa, nEW);

    // MMfa 2 (output overwrites p_m — M1 no longer needed)
    run_mmfa(p_xv, p_xa, p_m);
    ew_mul_kernel<<<nEW / 256, 256>>>(p_m, p_vms, p_ov, nEW);
    ew_mul_kernel<<<nEW / 256, 256>>>(p_m, p_ams, p_oa, nEW);

    // out_layer: fv, fa written straight into d_out
    float* out = (float*)d_out;
    float* fv = out;
    float* fa = out + (size_t)Bn * LAT;          // 131072
    float* pv = fa + (size_t)Bn * LAT;           // 262144
    float* pa = pv + (size_t)Bn * 10;            // 272384

    launch_gemm(p_ov, out_W1, out_b1, p_h, Bn, OUT1, SD, 1);
    launch_gemm(p_h,  out_W2, out_b2, fv,  Bn, LAT, OUT1, 0);
    launch_gemm(p_oa, out_W1, out_b1, p_h, Bn, OUT1, SD, 1);
    launch_gemm(p_h,  out_W2, out_b2, fa,  Bn, LAT, OUT1, 0);

    cls_kernel<<<Bn / 8, 256>>>(fv, clsvW1, clsvW2, pv);
    cls_kernel<<<Bn / 8, 256>>>(fa, clsaW1, clsaW2, pa);
}

// round 2
// speedup vs baseline: 2.6166x; 2.6166x over previous
#include <cuda_runtime.h>
#include <math.h>
#include <stdint.h>

// ---------------- problem constants ----------------
static constexpr int Bn   = 1024;
static constexpr int ENC  = 1024;
static constexpr int M3   = 3072;   // B*S
static constexpr int Dd   = 256;
static constexpr int SD   = 768;
static constexpr int OUT1 = 512;
static constexpr int LAT  = 128;

static constexpr size_t N_BE  = (size_t)Bn * ENC;
static constexpr size_t N_BSD = (size_t)M3 * Dd;

__device__ float g_scratch[2 * N_BE + 20 * N_BSD + (size_t)Bn * OUT1];

__device__ __forceinline__ float sigm(float x) { return 1.0f / (1.0f + expf(-x)); }

__device__ __forceinline__ unsigned tf32r(float x) {
    unsigned r;
    asm("cvt.rna.tf32.f32 %0, %1;" : "=r"(r) : "f"(x));
    return r;
}

__device__ __forceinline__ void mma_tf32(float& c0, float& c1, float& c2, float& c3,
                                         unsigned a0, unsigned a1, unsigned a2, unsigned a3,
                                         unsigned b0, unsigned b1) {
    asm("mma.sync.aligned.m16n8k8.row.col.f32.tf32.tf32.f32 "
        "{%0,%1,%2,%3}, {%4,%5,%6,%7}, {%8,%9}, {%0,%1,%2,%3};"
        : "+f"(c0), "+f"(c1), "+f"(c2), "+f"(c3)
        : "r"(a0), "r"(a1), "r"(a2), "r"(a3), "r"(b0), "r"(b1));
}

// ---------------- fp32 SIMT GEMM (kept for precision-critical layers) ----------------
#define BM 64
#define BN 64
#define BK 16

__global__ void __launch_bounds__(256) gemm_kernel(
    const float* __restrict__ A, const float* __restrict__ W,
    const float* __restrict__ bias, float* __restrict__ C,
    int M, int N, int K, int flags)
{
    __shared__ __align__(16) float As[BK][BM + 4];
    __shared__ __align__(16) float Ws[BK][BN + 4];
    const int tid = threadIdx.x;
    const int tx = tid & 15, ty = tid >> 4;
    const int m0 = blockIdx.y * BM, n0 = blockIdx.x * BN;
    const int lm = tid >> 2;
    const int lk = (tid & 3) << 2;
    const float* Ag = A + (size_t)(m0 + lm) * K + lk;
    const float* Wg = W + (size_t)(n0 + lm) * K + lk;

    float acc[4][4] = {};
    for (int kt = 0; kt < K; kt += BK) {
        float4 av = *(const float4*)(Ag + kt);
        float4 wv = *(const float4*)(Wg + kt);
        As[lk + 0][lm] = av.x; As[lk + 1][lm] = av.y;
        As[lk + 2][lm] = av.z; As[lk + 3][lm] = av.w;
        Ws[lk + 0][lm] = wv.x; Ws[lk + 1][lm] = wv.y;
        Ws[lk + 2][lm] = wv.z; Ws[lk + 3][lm] = wv.w;
        __syncthreads();
#pragma unroll
        for (int k = 0; k < BK; k++) {
            float4 a = *(const float4*)&As[k][ty << 2];
            float4 b = *(const float4*)&Ws[k][tx << 2];
            acc[0][0] = fmaf(a.x, b.x, acc[0][0]); acc[0][1] = fmaf(a.x, b.y, acc[0][1]);
            acc[0][2] = fmaf(a.x, b.z, acc[0][2]); acc[0][3] = fmaf(a.x, b.w, acc[0][3]);
            acc[1][0] = fmaf(a.y, b.x, acc[1][0]); acc[1][1] = fmaf(a.y, b.y, acc[1][1]);
            acc[1][2] = fmaf(a.y, b.z, acc[1][2]); acc[1][3] = fmaf(a.y, b.w, acc[1][3]);
            acc[2][0] = fmaf(a.z, b.x, acc[2][0]); acc[2][1] = fmaf(a.z, b.y, acc[2][1]);
            acc[2][2] = fmaf(a.z, b.z, acc[2][2]); acc[2][3] = fmaf(a.z, b.w, acc[2][3]);
            acc[3][0] = fmaf(a.w, b.x, acc[3][0]); acc[3][1] = fmaf(a.w, b.y, acc[3][1]);
            acc[3][2] = fmaf(a.w, b.z, acc[3][2]); acc[3][3] = fmaf(a.w, b.w, acc[3][3]);
        }
        __syncthreads();
    }
#pragma unroll
    for (int i = 0; i < 4; i++) {
#pragma unroll
        for (int j = 0; j < 4; j++) {
            int row = m0 + (ty << 2) + i;
            int col = n0 + (tx << 2) + j;
            float v = acc[i][j] + bias[col];
            if (flags & 1) v = fmaxf(v, 0.0f);
            size_t idx = (size_t)row * N + col;
            if (flags & 2) C[idx] += v; else C[idx] = v;
        }
    }
}

// ---------------- tf32 tensor-core GEMM: C = op(A[M,K] @ W[N,K]^T + bias) ----------------
// BM=64, BN=64, BK=16, 128 threads = 4 warps (2m x 2n), warp tile 32x32.
__global__ void __launch_bounds__(128) mma_gemm_kernel(
    const float* __restrict__ A, const float* __restrict__ W,
    const float* __restrict__ bias, float* __restrict__ C,
    int M, int N, int K, int flags)
{
    __shared__ float As[16][72];   // k-major: As[k][m]
    __shared__ float Ws[16][72];   // k-major: Ws[k][n]
    const int tid = threadIdx.x;
    const int lane = tid & 31, wid = tid >> 5;
    const int wm = wid >> 1, wn = wid & 1;
    const int m0 = blockIdx.y * 64, n0 = blockIdx.x * 64;
    const int c4 = lane & 3, lr = lane >> 2;

    float c[2][4][4];
#pragma unroll
    for (int mt = 0; mt < 2; mt++)
#pragma unroll
        for (int nt = 0; nt < 4; nt++)
#pragma unroll
            for (int e = 0; e < 4; e++) c[mt][nt][e] = 0.0f;

    // per-tile loader mapping: f = tid + 128u (u<2): row = f>>2, sq = f&3
    const int lrow = tid >> 2, lsq = tid & 3;
    float4 pa[2], pw[2];
#pragma unroll
    for (int u = 0; u < 2; u++) {
        int row = lrow + u * 32;
        pa[u] = *(const float4*)(A + (size_t)(m0 + row) * K + lsq * 4);
        pw[u] = *(const float4*)(W + (size_t)(n0 + row) * K + lsq * 4);
    }

    const int ktiles = K >> 4;
    for (int kt = 0; kt < ktiles; kt++) {
        // store prefetched regs to smem (tf32-rounded)
#pragma unroll
        for (int u = 0; u < 2; u++) {
            int row = lrow + u * 32;
            As[lsq * 4 + 0][row] = __uint_as_float(tf32r(pa[u].x));
            As[lsq * 4 + 1][row] = __uint_as_float(tf32r(pa[u].y));
            As[lsq * 4 + 2][row] = __uint_as_float(tf32r(pa[u].z));
            As[lsq * 4 + 3][row] = __uint_as_float(tf32r(pa[u].w));
            Ws[lsq * 4 + 0][row] = __uint_as_float(tf32r(pw[u].x));
            Ws[lsq * 4 + 1][row] = __uint_as_float(tf32r(pw[u].y));
            Ws[lsq * 4 + 2][row] = __uint_as_float(tf32r(pw[u].z));
            Ws[lsq * 4 + 3][row] = __uint_as_float(tf32r(pw[u].w));
        }
        __syncthreads();
        if (kt + 1 < ktiles) {
            int koff = (kt + 1) * 16 + lsq * 4;
#pragma unroll
            for (int u = 0; u < 2; u++) {
                int row = lrow + u * 32;
                pa[u] = *(const float4*)(A + (size_t)(m0 + row) * K + koff);
                pw[u] = *(const float4*)(W + (size_t)(n0 + row) * K + koff);
            }
        }
#pragma unroll
        for (int kk = 0; kk < 16; kk += 8) {
            unsigned a[2][4];
#pragma unroll
            for (int mt = 0; mt < 2; mt++) {
                int rb = wm * 32 + mt * 16 + lr;
                a[mt][0] = __float_as_uint(As[kk + c4][rb]);
                a[mt][1] = __float_as_uint(As[kk + c4][rb + 8]);
                a[mt][2] = __float_as_uint(As[kk + c4 + 4][rb]);
                a[mt][3] = __float_as_uint(As[kk + c4 + 4][rb + 8]);
            }
#pragma unroll
            for (int nt = 0; nt < 4; nt++) {
                int nb = wn * 32 + nt * 8 + lr;
                unsigned b0 = __float_as_uint(Ws[kk + c4][nb]);
                unsigned b1 = __float_as_uint(Ws[kk + c4 + 4][nb]);
#pragma unroll
                for (int mt = 0; mt < 2; mt++)
                    mma_tf32(c[mt][nt][0], c[mt][nt][1], c[mt][nt][2], c[mt][nt][3],
                             a[mt][0], a[mt][1], a[mt][2], a[mt][3], b0, b1);
            }
        }
        __syncthreads();
    }

#pragma unroll
    for (int mt = 0; mt < 2; mt++) {
#pragma unroll
        for (int nt = 0; nt < 4; nt++) {
            int row = m0 + wm * 32 + mt * 16 + lr;
            int col = n0 + wn * 32 + nt * 8 + c4 * 2;
#pragma unroll
            for (int e = 0; e < 4; e++) {
                int rr = row + (e >> 1) * 8;
                int cc = col + (e & 1);
                float v = c[mt][nt][e] + bias[cc];
                if (flags & 1) v = fmaxf(v, 0.0f);
                size_t idx = (size_t)rr * N + cc;
                if (flags & 2) C[idx] += v; else C[idx] = v;
            }
        }
    }
}

// ---------------- tf32 bilinear: J[r,o] = sigmoid( sum_{i,j} cva[r,i] W[o,i,j] cav[r,j] ) ----
// GEMM view: K = 65536 (k = i*256+j), A = E generated on the fly, B = Wflat.
// grid (48, 4), 128 threads = 4 warps (2m x 2n), warp tile 32x32, BM=BN=64.
// smem: s_cva[64][260], s_cav[64][260] (raw fp32), s_W[2][64][68] (o-major, tf32-rounded).
static constexpr int BIL_SMEM_FLOATS = 2 * 64 * 260 + 2 * 64 * 68;

__global__ void __launch_bounds__(128) bilinear_tf32_kernel(
    const float* __restrict__ cva, const float* __restrict__ cav,
    const float* __restrict__ Wb, float* __restrict__ Jout)
{
    extern __shared__ float sm[];
    float* s_cva = sm;                         // [64][260]
    float* s_cav = sm + 64 * 260;              // [64][260]
    float* s_W   = s_cav + 64 * 260;           // [2][64][68]

    const int tid = threadIdx.x;
    const int lane = tid & 31, wid = tid >> 5;
    const int wm = wid >> 1, wn = wid & 1;
    const int r0 = blockIdx.x * 64, o0 = blockIdx.y * 64;
    const int c4 = lane & 3, lr = lane >> 2;

    // load cva/cav rows [r0, r0+64) : 4096 float4 each
    for (int f = tid; f < 4096; f += 128) {
        int row = f >> 6, q4 = f & 63;
        float4 v = *(const float4*)(cva + (size_t)(r0 + row) * 256 + q4 * 4);
        float4 w = *(const float4*)(cav + (size_t)(r0 + row) * 256 + q4 * 4);
        *(float4*)&s_cva[row * 260 + q4 * 4] = v;
        *(float4*)&s_cav[row * 260 + q4 * 4] = w;
    }

    float c[2][4][4];
#pragma unroll
    for (int mt = 0; mt < 2; mt++)
#pragma unroll
        for (int nt = 0; nt < 4; nt++)
#pragma unroll
            for (int e = 0; e < 4; e++) c[mt][nt][e] = 0.0f;

    // W tile loader: per (i,h): [64 o][64 k], 1024 float4, 8 per thread
    // f = tid + 128u: o = f>>4, kq = f&15
    const int lo = tid >> 4, lkq = tid & 15;     // per-u base: o = lo + u*8
    float4 wreg[8];
#pragma unroll
    for (int u = 0; u < 8; u++) {
        int o = lo + u * 8;
        wreg[u] = *(const float4*)(Wb + (size_t)(o0 + o) * 65536 + lkq * 4);
    }
    __syncthreads();   // cva/cav ready

    const int r_mt0 = wm * 32 + lr;   // thread row base (mt adds 16, +8 variants)

    for (int it = 0; it < 1024; it++) {
        const int buf = it & 1;
        const int i = it >> 2, h = it & 3;
        // store prefetched W regs into smem buf (tf32-rounded)
        float* wb = s_W + buf * 64 * 68;
#pragma unroll
        for (int u = 0; u < 8; u++) {
            int o = lo + u * 8;
            float* dst = wb + o * 68 + lkq * 4;
            dst[0] = __uint_as_float(tf32r(wreg[u].x));
            dst[1] = __uint_as_float(tf32r(wreg[u].y));
            dst[2] = __uint_as_float(tf32r(wreg[u].z));
            dst[3] = __uint_as_float(tf32r(wreg[u].w));
        }
        // issue next tile's global loads
        if (it + 1 < 1024) {
            int i2 = (it + 1) >> 2, h2 = (it + 1) & 3;
            const float* gsrc = Wb + (size_t)o0 * 65536 + (size_t)i2 * 256 + h2 * 64 + lkq * 4;
#pragma unroll
            for (int u = 0; u < 8; u++) {
                int o = lo + u * 8;
                wreg[u] = *(const float4*)(gsrc + (size_t)o * 65536);
            }
        }
        // cva scalars for this i (reload each it; L1/smem cheap, 4 lds per it)
        float s00 = s_cva[(r_mt0) * 260 + i];
        float s01 = s_cva[(r_mt0 + 8) * 260 + i];
        float s10 = s_cva[(r_mt0 + 16) * 260 + i];
        float s11 = s_cva[(r_mt0 + 24) * 260 + i];
        __syncthreads();   // W buf ready, previous buf reads done

#pragma unroll
        for (int jc = 0; jc < 8; jc++) {
            const int j0 = h * 64 + jc * 8;
            unsigned a[2][4];
            {
                float cv0 = s_cav[(r_mt0) * 260 + j0 + c4];
                float cv1 = s_cav[(r_mt0 + 8) * 260 + j0 + c4];
                float cv2 = s_cav[(r_mt0) * 260 + j0 + c4 + 4];
                float cv3 = s_cav[(r_mt0 + 8) * 260 + j0 + c4 + 4];
                a[0][0] = tf32r(s00 * cv0);
                a[0][1] = tf32r(s01 * cv1);
                a[0][2] = tf32r(s00 * cv2);
                a[0][3] = tf32r(s01 * cv3);
                cv0 = s_cav[(r_mt0 + 16) * 260 + j0 + c4];
                cv1 = s_cav[(r_mt0 + 24) * 260 + j0 + c4];
                cv2 = s_cav[(r_mt0 + 16) * 260 + j0 + c4 + 4];
                cv3 = s_cav[(r_mt0 + 24) * 260 + j0 + c4 + 4];
                a[1][0] = tf32r(s10 * cv0);
                a[1][1] = tf32r(s11 * cv1);
                a[1][2] = tf32r(s10 * cv2);
                a[1][3] = tf32r(s11 * cv3);
            }
            const int kk = jc * 8;
#pragma unroll
            for (int nt = 0; nt < 4; nt++) {
                int nb = wn * 32 + nt * 8 + lr;
                unsigned b0 = __float_as_uint(wb[nb * 68 + kk + c4]);
                unsigned b1 = __float_as_uint(wb[nb * 68 + kk + c4 + 4]);
#pragma unroll
                for (int mt = 0; mt < 2; mt++)
                    mma_tf32(c[mt][nt][0], c[mt][nt][1], c[mt][nt][2], c[mt][nt][3],
                             a[mt][0], a[mt][1], a[mt][2], a[mt][3], b0, b1);
            }
        }
        __syncthreads();
    }

#pragma unroll
    for (int mt = 0; mt < 2; mt++) {
#pragma unroll
        for (int nt = 0; nt < 4; nt++) {
            int row = r0 + wm * 32 + mt * 16 + lr;
            int col = o0 + wn * 32 + nt * 8 + c4 * 2;
            Jout[(size_t)row * 256 + col]             = sigm(c[mt][nt][0]);
            Jout[(size_t)row * 256 + col + 1]         = sigm(c[mt][nt][1]);
            Jout[(size_t)(row + 8) * 256 + col]       = sigm(c[mt][nt][2]);
            Jout[(size_t)(row + 8) * 256 + col + 1]   = sigm(c[mt][nt][3]);
        }
    }
}

// ---------------- attention kernel (unchanged) ----------------
__global__ void __launch_bounds__(256) attn_kernel(
    const float* __restrict__ xv, const float* __restrict__ xa,
    const float* __restrict__ qv, const float* __restrict__ qa,
    const float* __restrict__ kv, const float* __restrict__ ka,
    float* __restrict__ ava, float* __restrict__ av_,
    float* __restrict__ aav, float* __restrict__ aa_)
{
    __shared__ float s_x[2][3][256];
    __shared__ float s_q[2][3][256];
    __shared__ float s_k[2][3][256];
    __shared__ float s_sc[4][3][3];
    const int tid = threadIdx.x;
    const size_t base = (size_t)blockIdx.x * 768;

    float* fx = &s_x[0][0][0];
    float* fq = &s_q[0][0][0];
    float* fk = &s_k[0][0][0];
    for (int idx = tid; idx < 768; idx += 256) {
        fx[idx] = xv[base + idx]; fx[768 + idx] = xa[base + idx];
        fq[idx] = qv[base + idx]; fq[768 + idx] = qa[base + idx];
        fk[idx] = kv[base + idx]; fk[768 + idx] = ka[base + idx];
    }
    __syncthreads();

    const int w = tid >> 5, lane = tid & 31;
    for (int task = w; task < 36; task += 8) {
        int type = task / 9, rem = task % 9, s3 = rem / 3, t3 = rem % 3;
        int qsel = type >> 1;
        int ksel = (type == 0 || type == 3) ? 1 : 0;
        float sum = 0.0f;
        for (int d = lane; d < 256; d += 32) sum += s_q[qsel][s3][d] * s_k[ksel][t3][d];
#pragma unroll
        for (int off = 16; off; off >>= 1) sum += __shfl_down_sync(0xffffffffu, sum, off);
        if (lane == 0) s_sc[type][s3][t3] = sum;
    }
    __syncthreads();

    if (tid < 12) {
        int type = tid / 3, s3 = tid % 3;
        float a = s_sc[type][s3][0], b = s_sc[type][s3][1], c = s_sc[type][s3][2];
        float m = fmaxf(a, fmaxf(b, c));
        float ea = expf(a - m), eb = expf(b - m), ec = expf(c - m);
        float inv = 0.0625f / (ea + eb + ec);
        s_sc[type][s3][0] = ea * inv; s_sc[type][s3][1] = eb * inv; s_sc[type][s3][2] = ec * inv;
    }
    __syncthreads();

    for (int idx = tid; idx < 3072; idx += 256) {
        int type = idx / 768, rem = idx % 768;
        int s3 = rem >> 8, d = rem & 255;
        int xsel = (type == 0 || type == 3) ? 1 : 0;
        float v = s_sc[type][s3][0] * s_x[xsel][0][d]
                + s_sc[type][s3][1] * s_x[xsel][1][d]
                + s_sc[type][s3][2] * s_x[xsel][2][d];
        float* outp = (type == 0) ? ava : (type == 1) ? av_ : (type == 2) ? aav : aa_;
        outp[base + rem] = v;
    }
}

// ---------------- elementwise kernels ----------------
__global__ void ew_sigmul_kernel(const float* __restrict__ L, const float* __restrict__ a,
                                 float* __restrict__ out, int n)
{
    int i = blockIdx.x * 256 + threadIdx.x;
    if (i < n) out[i] = sigm(L[i] * a[i]);
}

__global__ void ew_mul_kernel(const float* __restrict__ a, const float* __restrict__ b,
                              float* __restrict__ out, int n)
{
    int i = blockIdx.x * 256 + threadIdx.x;
    if (i < n) out[i] = a[i] * b[i];
}

__global__ void ew_combine_kernel(const float* __restrict__ j, const float* __restrict__ xv,
                                  const float* __restrict__ xa, const float* __restrict__ tcp,
                                  float* __restrict__ out, int n)
{
    int i = blockIdx.x * 256 + threadIdx.x;
    if (i < n) {
        float tc = *tcp;
        float jv = j[i];
        out[i] = tc * jv * xv[i] + (1.0f - jv) * xa[i];
    }
}

// ---------------- classifier ----------------
__global__ void __launch_bounds__(256) cls_kernel(
    const float* __restrict__ F, const float* __restrict__ W1,
    const float* __restrict__ W2, float* __restrict__ P)
{
    __shared__ float s_f[8][128];
    __shared__ float s_w1[32][129];
    __shared__ float s_w2[320];
    __shared__ float s_h[8][32];
    const int tid = threadIdx.x;
    const int r0 = blockIdx.x * 8;
    for (int idx = tid; idx < 1024; idx += 256) s_f[idx >> 7][idx & 127] = F[(size_t)r0 * 128 + idx];
    for (int idx = tid; idx < 4096; idx += 256) s_w1[idx >> 7][idx & 127] = W1[idx];
    for (int idx = tid; idx < 320; idx += 256) s_w2[idx] = W2[idx];
    __syncthreads();
    const int w = tid >> 5, lane = tid & 31;
    float h = 0.0f;
#pragma unroll 8
    for (int d = 0; d < 128; d++) h = fmaf(s_f[w][d], s_w1[lane][d], h);
    s_h[w][lane] = fmaxf(h, 0.0f);
    __syncwarp();
    if (lane < 10) {
        float p = 0.0f;
#pragma unroll
        for (int k = 0; k < 32; k++) p = fmaf(s_h[w][k], s_w2[lane * 32 + k], p);
        P[(size_t)(r0 + w) * 10 + lane] = p;
    }
}

// ---------------- host ----------------
static void launch_gemm(const float* A, const float* W, const float* b, float* C,
                        int M, int N, int K, int flags)
{
    dim3 grid(N / BN, M / BM);
    gemm_kernel<<<grid, 256>>>(A, W, b, C, M, N, K, flags);
}

static void launch_mma_gemm(const float* A, const float* W, const float* b, float* C,
                            int M, int N, int K, int flags)
{
    dim3 grid(N / 64, M / 64);
    mma_gemm_kernel<<<grid, 128>>>(A, W, b, C, M, N, K, flags);
}

extern "C" void kernel_launch(void* const* d_in, const int* in_sizes, int n_in,
                              void* d_out, int out_size)
{
    const float* img    = (const float*)d_in[0];
    const float* audio  = (const float*)d_in[1];
    const float* vis_W  = (const float*)d_in[2];
    const float* vis_b  = (const float*)d_in[3];
    const float* aud_W  = (const float*)d_in[4];
    const float* aud_b  = (const float*)d_in[5];
    const float* msv_W  = (const float*)d_in[6];
    const float* msv_b  = (const float*)d_in[7];
    const float* msa_W  = (const float*)d_in[8];
    const float* msa_b  = (const float*)d_in[9];
    const float* mmfaW  = (const float*)d_in[10];
    const float* mmfaB  = (const float*)d_in[11];
    const float* bilW   = (const float*)d_in[12];
    const float* t_c    = (const float*)d_in[13];
    const float* out_W1 = (const float*)d_in[14];
    const float* out_b1 = (const float*)d_in[15];
    const float* out_W2 = (const float*)d_in[16];
    const float* out_b2 = (const float*)d_in[17];
    const float* clsvW1 = (const float*)d_in[18];
    const float* clsvW2 = (const float*)d_in[19];
    const float* clsaW1 = (const float*)d_in[20];
    const float* clsaW2 = (const float*)d_in[21];

    float* S = nullptr;
    cudaGetSymbolAddress((void**)&S, g_scratch);

    float* p_vis = S;
    float* p_aud = p_vis + N_BE;
    float* p_vms = p_aud + N_BE;
    float* p_ams = p_vms + N_BSD;
    float* p_xv  = p_ams + N_BSD;
    float* p_xa  = p_xv  + N_BSD;
    float* p_qv  = p_xa  + N_BSD;
    float* p_qa  = p_qv  + N_BSD;
    float* p_kv  = p_qa  + N_BSD;
    float* p_ka  = p_kv  + N_BSD;
    float* p_ava = p_ka  + N_BSD;
    float* p_av  = p_ava + N_BSD;
    float* p_aav = p_av  + N_BSD;
    float* p_aa  = p_aav + N_BSD;
    float* p_L45 = p_aa  + N_BSD;
    float* p_L67 = p_L45 + N_BSD;
    float* p_cva = p_L67 + N_BSD;
    float* p_cav = p_cva + N_BSD;
    float* p_j   = p_cav + N_BSD;
    float* p_m   = p_j   + N_BSD;
    float* p_ov  = p_m   + N_BSD;
    float* p_oa  = p_ov  + N_BSD;
    float* p_h   = p_oa  + N_BSD;

    const int nEW = (int)N_BSD;

    // allow big dynamic smem for the bilinear kernel
    cudaFuncSetAttribute(bilinear_tf32_kernel,
                         cudaFuncAttributeMaxDynamicSharedMemorySize,
                         BIL_SMEM_FLOATS * (int)sizeof(float));

    auto run_mmfa = [&](const float* xv, const float* xa, float* outm) {
        launch_mma_gemm(xv, mmfaW + 0 * 65536, mmfaB + 0 * 256, p_qv, M3, Dd, Dd, 0);
        launch_mma_gemm(xa, mmfaW + 1 * 65536, mmfaB + 1 * 256, p_qa, M3, Dd, Dd, 0);
        launch_mma_gemm(xv, mmfaW + 2 * 65536, mmfaB + 2 * 256, p_kv, M3, Dd, Dd, 0);
        launch_mma_gemm(xa, mmfaW + 3 * 65536, mmfaB + 3 * 256, p_ka, M3, Dd, Dd, 0);
        attn_kernel<<<Bn, 256>>>(xv, xa, p_qv, p_qa, p_kv, p_ka, p_ava, p_av, p_aav, p_aa);
        launch_mma_gemm(p_ava, mmfaW + 4 * 65536, mmfaB + 4 * 256, p_L45, M3, Dd, Dd, 0);
        launch_mma_gemm(p_av,  mmfaW + 5 * 65536, mmfaB + 5 * 256, p_L45, M3, Dd, Dd, 2);
        launch_mma_gemm(p_aav, mmfaW + 6 * 65536, mmfaB + 6 * 256, p_L67, M3, Dd, Dd, 0);
        launch_mma_gemm(p_aa,  mmfaW + 7 * 65536, mmfaB + 7 * 256, p_L67, M3, Dd, Dd, 2);
        ew_sigmul_kernel<<<nEW / 256, 256>>>(p_L45, p_av, p_cva, nEW);
        ew_sigmul_kernel<<<nEW / 256, 256>>>(p_L67, p_aa, p_cav, nEW);
        dim3 bg(48, 4);
        bilinear_tf32_kernel<<<bg, 128, BIL_SMEM_FLOATS * (int)sizeof(float)>>>(
            p_cva, p_cav, bilW, p_j);
        ew_combine_kernel<<<nEW / 256, 256>>>(p_j, xv, xa, t_c, outm, nEW);
    };

    // encoders + multi-scale (fp32 SIMT for precision headroom)
    launch_gemm(img,   vis_W, vis_b, p_vis, Bn, ENC, 4096, 1);
    launch_gemm(audio, aud_W, aud_b, p_aud, Bn, ENC, 1024, 1);
    launch_gemm(p_vis, msv_W, msv_b, p_vms, Bn, SD, ENC, 1);
    launch_gemm(p_aud, msa_W, msa_b, p_ams, Bn, SD, ENC, 1);

    // MMfa 1
    run_mmfa(p_vms, p_ams, p_m);
    ew_mul_kernel<<<nEW / 256, 256>>>(p_m, p_vms, p_xv, nEW);
    ew_mul_kernel<<<nEW / 256, 256>>>(p_m, p_ams, p_xa, nEW);

    // MMfa 2
    run_mmfa(p_xv, p_xa, p_m);
    ew_mul_kernel<<<nEW / 256, 256>>>(p_m, p_vms, p_ov, nEW);
    ew_mul_kernel<<<nEW / 256, 256>>>(p_m, p_ams, p_oa, nEW);

    // out_layer
    float* out = (float*)d_out;
    float* fv = out;
    float* fa = out + (size_t)Bn * LAT;
    float* pv = fa + (size_t)Bn * LAT;
    float* pa = pv + (size_t)Bn * 10;

    launch_gemm(p_ov, out_W1, out_b1, p_h, Bn, OUT1, SD, 1);
    launch_gemm(p_h,  out_W2, out_b2, fv,  Bn, LAT, OUT1, 0);
    launch_gemm(p_oa, out_W1, out_b1, p_h, Bn, OUT1, SD, 1);
    launch_gemm(p_h,  out_W2, out_b2, fa,  Bn, LAT, OUT1, 0);

    cls_kernel<<<Bn / 8, 256>>>(fv, clsvW1, clsvW2, pv);
    cls_kernel<<<Bn / 8, 256>>>(fa, clsaW1, clsaW2, pa);
}

// round 4
// speedup vs baseline: 6.7410x; 2.5763x over previous
#include <cuda_runtime.h>
#include <cuda_fp16.h>
#include <math.h>
#include <stdint.h>

// ---------------- problem constants ----------------
static constexpr int Bn   = 1024;
static constexpr int M3   = 3072;   // B*S
static constexpr int Dd   = 256;
static constexpr int SD   = 768;
static constexpr int OUT1 = 512;
static constexpr int LAT  = 128;

static constexpr size_t N_BE  = (size_t)Bn * 1024;
static constexpr size_t N_BSD = (size_t)M3 * Dd;     // 786432

__device__ float g_scratch[2 * N_BE + 22 * N_BSD + (size_t)Bn * OUT1];
__device__ float g_bias_fused[512];   // [0:256)=b4+b5, [256:512)=b6+b7

__device__ __forceinline__ float sigm(float x) { return 1.0f / (1.0f + expf(-x)); }

__device__ __forceinline__ unsigned tf32r(float x) {
    unsigned r;
    asm("cvt.rna.tf32.f32 %0, %1;" : "=r"(r) : "f"(x));
    return r;
}

__device__ __forceinline__ void mma_tf32(float& c0, float& c1, float& c2, float& c3,
                                         unsigned a0, unsigned a1, unsigned a2, unsigned a3,
                                         unsigned b0, unsigned b1) {
    asm("mma.sync.aligned.m16n8k8.row.col.f32.tf32.tf32.f32 "
        "{%0,%1,%2,%3}, {%4,%5,%6,%7}, {%8,%9}, {%0,%1,%2,%3};"
        : "+f"(c0), "+f"(c1), "+f"(c2), "+f"(c3)
        : "r"(a0), "r"(a1), "r"(a2), "r"(a3), "r"(b0), "r"(b1));
}

__device__ __forceinline__ void mma_f16(float& c0, float& c1, float& c2, float& c3,
                                        unsigned a0, unsigned a1, unsigned a2, unsigned a3,
                                        unsigned b0, unsigned b1) {
    asm("mma.sync.aligned.m16n8k16.row.col.f32.f16.f16.f32 "
        "{%0,%1,%2,%3}, {%4,%5,%6,%7}, {%8,%9}, {%0,%1,%2,%3};"
        : "+f"(c0), "+f"(c1), "+f"(c2), "+f"(c3)
        : "r"(a0), "r"(a1), "r"(a2), "r"(a3), "r"(b0), "r"(b1));
}

// ---------------- bias-fusion helper (file-scope; fixes round-3 compile error) ----------------
__global__ void fuse_bias_kernel(const float* __restrict__ b, float* __restrict__ o)
{
    int i = threadIdx.x;
    o[i]       = b[4 * 256 + i] + b[5 * 256 + i];
    o[256 + i] = b[6 * 256 + i] + b[7 * 256 + i];
}

// ---------------- tf32 tensor GEMM with split-W (K-concat) + fused epilogue ----------------
// C[M,N] = epi( A[M,K] @ Wcat^T + bias ), Wcat row n = [W[n,0:Ka] | W2[n,0:K-Ka]]
// flags: bit0 relu ; bit2 sigmul: out = sigm(v * E[row*eld + eoff + col])
__global__ void __launch_bounds__(128) mma_gemm_kernel(
    const float* __restrict__ A, const float* __restrict__ W, const float* __restrict__ W2,
    const float* __restrict__ bias, float* __restrict__ C,
    int M, int N, int K, int Ka, int flags,
    const float* __restrict__ E, int eld, int eoff)
{
    __shared__ float As[16][72];
    __shared__ float Ws[16][72];
    const int tid = threadIdx.x;
    const int lane = tid & 31, wid = tid >> 5;
    const int wm = wid >> 1, wn = wid & 1;
    const int m0 = blockIdx.y * 64, n0 = blockIdx.x * 64;
    const int c4 = lane & 3, lr = lane >> 2;
    const int Kb = K - Ka;

    float c[2][4][4];
#pragma unroll
    for (int mt = 0; mt < 2; mt++)
#pragma unroll
        for (int nt = 0; nt < 4; nt++)
#pragma unroll
            for (int e = 0; e < 4; e++) c[mt][nt][e] = 0.0f;

    const int lrow = tid >> 2, lsq = tid & 3;
    float4 pa[2], pw[2];
    {
        int k = lsq * 4;
#pragma unroll
        for (int u = 0; u < 2; u++) {
            int row = lrow + u * 32;
            pa[u] = *(const float4*)(A + (size_t)(m0 + row) * K + k);
            const float* ws = (k < Ka) ? (W + (size_t)(n0 + row) * Ka + k)
                                       : (W2 + (size_t)(n0 + row) * Kb + (k - Ka));
            pw[u] = *(const float4*)ws;
        }
    }

    const int ktiles = K >> 4;
    for (int kt = 0; kt < ktiles; kt++) {
#pragma unroll
        for (int u = 0; u < 2; u++) {
            int row = lrow + u * 32;
            As[lsq * 4 + 0][row] = __uint_as_float(tf32r(pa[u].x));
            As[lsq * 4 + 1][row] = __uint_as_float(tf32r(pa[u].y));
            As[lsq * 4 + 2][row] = __uint_as_float(tf32r(pa[u].z));
            As[lsq * 4 + 3][row] = __uint_as_float(tf32r(pa[u].w));
            Ws[lsq * 4 + 0][row] = __uint_as_float(tf32r(pw[u].x));
            Ws[lsq * 4 + 1][row] = __uint_as_float(tf32r(pw[u].y));
            Ws[lsq * 4 + 2][row] = __uint_as_float(tf32r(pw[u].z));
            Ws[lsq * 4 + 3][row] = __uint_as_float(tf32r(pw[u].w));
        }
        __syncthreads();
        if (kt + 1 < ktiles) {
            int k = (kt + 1) * 16 + lsq * 4;
#pragma unroll
            for (int u = 0; u < 2; u++) {
                int row = lrow + u * 32;
                pa[u] = *(const float4*)(A + (size_t)(m0 + row) * K + k);
                const float* ws = (k < Ka) ? (W + (size_t)(n0 + row) * Ka + k)
                                           : (W2 + (size_t)(n0 + row) * Kb + (k - Ka));
                pw[u] = *(const float4*)ws;
            }
        }
#pragma unroll
        for (int kk = 0; kk < 16; kk += 8) {
            unsigned a[2][4];
#pragma unroll
            for (int mt = 0; mt < 2; mt++) {
                int rb = wm * 32 + mt * 16 + lr;
                a[mt][0] = __float_as_uint(As[kk + c4][rb]);
                a[mt][1] = __float_as_uint(As[kk + c4][rb + 8]);
                a[mt][2] = __float_as_uint(As[kk + c4 + 4][rb]);
                a[mt][3] = __float_as_uint(As[kk + c4 + 4][rb + 8]);
            }
#pragma unroll
            for (int nt = 0; nt < 4; nt++) {
                int nb = wn * 32 + nt * 8 + lr;
                unsigned b0 = __float_as_uint(Ws[kk + c4][nb]);
                unsigned b1 = __float_as_uint(Ws[kk + c4 + 4][nb]);
#pragma unroll
                for (int mt = 0; mt < 2; mt++)
                    mma_tf32(c[mt][nt][0], c[mt][nt][1], c[mt][nt][2], c[mt][nt][3],
                             a[mt][0], a[mt][1], a[mt][2], a[mt][3], b0, b1);
            }
        }
        __syncthreads();
    }

#pragma unroll
    for (int mt = 0; mt < 2; mt++) {
#pragma unroll
        for (int nt = 0; nt < 4; nt++) {
            int row = m0 + wm * 32 + mt * 16 + lr;
            int col = n0 + wn * 32 + nt * 8 + c4 * 2;
#pragma unroll
            for (int e = 0; e < 4; e++) {
                int rr = row + (e >> 1) * 8;
                int cc = col + (e & 1);
                float v = c[mt][nt][e] + bias[cc];
                if (flags & 1) v = fmaxf(v, 0.0f);
                if (flags & 4) v = sigm(v * E[(size_t)rr * eld + eoff + cc]);
                C[(size_t)rr * N + cc] = v;
            }
        }
    }
}

// ---------------- fp16 bilinear with K-split ----------------
// part[ks][r][o] = sum_{i in ks-range, j} cva[r,i] W[o,i,j] cav[r,j]
// grid (48, 2, 4): r-block 64, o-block 128, i-range 64. 256 threads = 8 warps (2m x 4n).
static constexpr int BIL_SMEM_BYTES = (2 * 64 * 264 + 2 * 128 * 72) * 2;

__global__ void __launch_bounds__(256) bilinear_f16_kernel(
    const float* __restrict__ cva, const float* __restrict__ cav,
    const float* __restrict__ Wb, float* __restrict__ part)
{
    extern __shared__ __half smh[];
    __half* s_cva = smh;                       // [64][264]
    __half* s_cav = smh + 64 * 264;            // [64][264]
    __half* s_W   = smh + 2 * 64 * 264;        // [2][128][72]

    const int tid = threadIdx.x;
    const int lane = tid & 31, wid = tid >> 5;
    const int wm = wid >> 2, wn = wid & 3;     // 2m x 4n
    const int g = lane >> 2, q = lane & 3;
    const int r0 = blockIdx.x * 64, o0 = blockIdx.y * 128;
    const int iBase = blockIdx.z * 64;

    // load cva/cav rows, fp32 -> fp16
    for (int f = tid; f < 4096; f += 256) {
        int row = f >> 6, q4 = f & 63;
        float4 v = *(const float4*)(cva + (size_t)(r0 + row) * 256 + q4 * 4);
        float4 w = *(const float4*)(cav + (size_t)(r0 + row) * 256 + q4 * 4);
        __half* d1 = s_cva + row * 264 + q4 * 4;
        __half* d2 = s_cav + row * 264 + q4 * 4;
        *(__half2*)(d1)     = __floats2half2_rn(v.x, v.y);
        *(__half2*)(d1 + 2) = __floats2half2_rn(v.z, v.w);
        *(__half2*)(d2)     = __floats2half2_rn(w.x, w.y);
        *(__half2*)(d2 + 2) = __floats2half2_rn(w.z, w.w);
    }

    float c[2][4][4];
#pragma unroll
    for (int mt = 0; mt < 2; mt++)
#pragma unroll
        for (int nt = 0; nt < 4; nt++)
#pragma unroll
            for (int e = 0; e < 4; e++) c[mt][nt][e] = 0.0f;

    // W prefetch: o = lo + 16u, float4 index lq within 64 j
    const int lo = tid >> 4, lq = tid & 15;
    float4 wreg[8];
    {
        const float* src = Wb + (size_t)(o0 + lo) * 65536 + (size_t)iBase * 256 + lq * 4;
#pragma unroll
        for (int u = 0; u < 8; u++) wreg[u] = *(const float4*)(src + (size_t)u * 16 * 65536);
    }
    __syncthreads();   // cva/cav ready

    const int rbase = wm * 32 + g;

    for (int it = 0; it < 256; it++) {
        __half* wbuf = s_W + (it & 1) * 128 * 72;
#pragma unroll
        for (int u = 0; u < 8; u++) {
            __half* dst = wbuf + (lo + 16 * u) * 72 + lq * 4;
            *(__half2*)(dst)     = __floats2half2_rn(wreg[u].x, wreg[u].y);
            *(__half2*)(dst + 2) = __floats2half2_rn(wreg[u].z, wreg[u].w);
        }
        if (it + 1 < 256) {
            int i2 = (it + 1) >> 2, h2 = (it + 1) & 3;
            const float* src = Wb + (size_t)(o0 + lo) * 65536
                             + (size_t)(iBase + i2) * 256 + h2 * 64 + lq * 4;
#pragma unroll
            for (int u = 0; u < 8; u++) wreg[u] = *(const float4*)(src + (size_t)u * 16 * 65536);
        }
        const int ig = iBase + (it >> 2);
        const int h = it & 3;
        __half2 s0 = __half2half2(s_cva[(rbase)      * 264 + ig]);
        __half2 s1 = __half2half2(s_cva[(rbase + 8)  * 264 + ig]);
        __half2 s2 = __half2half2(s_cva[(rbase + 16) * 264 + ig]);
        __half2 s3 = __half2half2(s_cva[(rbase + 24) * 264 + ig]);
        __syncthreads();   // wbuf ready; prev-buf reads done

#pragma unroll
        for (int jc = 0; jc < 4; jc++) {
            const int jlo = h * 64 + jc * 16 + 2 * q;
            const int jhi = jlo + 8;
            __half2 a[2][4];
            a[0][0] = __hmul2(*(__half2*)&s_cav[(rbase)      * 264 + jlo], s0);
            a[0][1] = __hmul2(*(__half2*)&s_cav[(rbase + 8)  * 264 + jlo], s1);
            a[0][2] = __hmul2(*(__half2*)&s_cav[(rbase)      * 264 + jhi], s0);
            a[0][3] = __hmul2(*(__half2*)&s_cav[(rbase + 8)  * 264 + jhi], s1);
            a[1][0] = __hmul2(*(__half2*)&s_cav[(rbase + 16) * 264 + jlo], s2);
            a[1][1] = __hmul2(*(__half2*)&s_cav[(rbase + 24) * 264 + jlo], s3);
            a[1][2] = __hmul2(*(__half2*)&s_cav[(rbase + 16) * 264 + jhi], s2);
            a[1][3] = __hmul2(*(__half2*)&s_cav[(rbase + 24) * 264 + jhi], s3);
            const int kloc = jc * 16;
#pragma unroll
            for (int nt = 0; nt < 4; nt++) {
                int oc = wn * 32 + nt * 8 + g;
                unsigned b0 = *(unsigned*)&wbuf[oc * 72 + kloc + 2 * q];
                unsigned b1 = *(unsigned*)&wbuf[oc * 72 + kloc + 2 * q + 8];
#pragma unroll
                for (int mt = 0; mt < 2; mt++)
                    mma_f16(c[mt][nt][0], c[mt][nt][1], c[mt][nt][2], c[mt][nt][3],
                            *(unsigned*)&a[mt][0], *(unsigned*)&a[mt][1],
                            *(unsigned*)&a[mt][2], *(unsigned*)&a[mt][3], b0, b1);
            }
        }
    }

    float* P = part + (size_t)blockIdx.z * N_BSD;
#pragma unroll
    for (int mt = 0; mt < 2; mt++) {
#pragma unroll
        for (int nt = 0; nt < 4; nt++) {
            int row = r0 + wm * 32 + mt * 16 + g;
            int col = o0 + wn * 32 + nt * 8 + q * 2;
            float* d0 = P + (size_t)row * 256 + col;
            float* d1 = P + (size_t)(row + 8) * 256 + col;
            d0[0] = c[mt][nt][0]; d0[1] = c[mt][nt][1];
            d1[0] = c[mt][nt][2]; d1[1] = c[mt][nt][3];
        }
    }
}

// finish: j = sigm(sum of 4 partials); out = tc*j*xv + (1-j)*xa
__global__ void bil_finish_kernel(const float* __restrict__ part,
                                  const float* __restrict__ xv, const float* __restrict__ xa,
                                  const float* __restrict__ tcp, float* __restrict__ out)
{
    int i = blockIdx.x * 256 + threadIdx.x;
    float s = part[i] + part[i + N_BSD] + part[i + 2 * N_BSD] + part[i + 3 * N_BSD];
    float j = sigm(s);
    out[i] = (*tcp) * j * xv[i] + (1.0f - j) * xa[i];
}

// ---------------- attention: writes K-concat buffers [r, 0:256]=alpha_x, [256:512]=alpha_self ----
__global__ void __launch_bounds__(256) attn_kernel(
    const float* __restrict__ xv, const float* __restrict__ xa,
    const float* __restrict__ qv, const float* __restrict__ qa,
    const float* __restrict__ kv, const float* __restrict__ ka,
    float* __restrict__ cat1, float* __restrict__ cat2)
{
    __shared__ float s_x[2][3][256];
    __shared__ float s_q[2][3][256];
    __shared__ float s_k[2][3][256];
    __shared__ float s_sc[4][3][3];
    const int tid = threadIdx.x;
    const size_t base = (size_t)blockIdx.x * 768;
    const size_t base2 = (size_t)blockIdx.x * 1536;

    float* fx = &s_x[0][0][0];
    float* fq = &s_q[0][0][0];
    float* fk = &s_k[0][0][0];
    for (int idx = tid; idx < 768; idx += 256) {
        fx[idx] = xv[base + idx]; fx[768 + idx] = xa[base + idx];
        fq[idx] = qv[base + idx]; fq[768 + idx] = qa[base + idx];
        fk[idx] = kv[base + idx]; fk[768 + idx] = ka[base + idx];
    }
    __syncthreads();

    const int w = tid >> 5, lane = tid & 31;
    for (int task = w; task < 36; task += 8) {
        int type = task / 9, rem = task % 9, s3 = rem / 3, t3 = rem % 3;
        int qsel = type >> 1;
        int ksel = (type == 0 || type == 3) ? 1 : 0;
        float sum = 0.0f;
        for (int d = lane; d < 256; d += 32) sum += s_q[qsel][s3][d] * s_k[ksel][t3][d];
#pragma unroll
        for (int off = 16; off; off >>= 1) sum += __shfl_down_sync(0xffffffffu, sum, off);
        if (lane == 0) s_sc[type][s3][t3] = sum;
    }
    __syncthreads();

    if (tid < 12) {
        int type = tid / 3, s3 = tid % 3;
        float a = s_sc[type][s3][0], b = s_sc[type][s3][1], c = s_sc[type][s3][2];
        float m = fmaxf(a, fmaxf(b, c));
        float ea = expf(a - m), eb = expf(b - m), ec = expf(c - m);
        float inv = 0.0625f / (ea + eb + ec);
        s_sc[type][s3][0] = ea * inv; s_sc[type][s3][1] = eb * inv; s_sc[type][s3][2] = ec * inv;
    }
    __syncthreads();

    // type 0: ava -> cat1 lo ; 1: av -> cat1 hi ; 2: aav -> cat2 lo ; 3: aa -> cat2 hi
    for (int idx = tid; idx < 3072; idx += 256) {
        int type = idx / 768, rem = idx % 768;
        int s3 = rem >> 8, d = rem & 255;
        int xsel = (type == 0 || type == 3) ? 1 : 0;
        float v = s_sc[type][s3][0] * s_x[xsel][0][d]
                + s_sc[type][s3][1] * s_x[xsel][1][d]
                + s_sc[type][s3][2] * s_x[xsel][2][d];
        float* dst = (type < 2) ? cat1 : cat2;
        dst[base2 + (size_t)s3 * 512 + ((type & 1) ? 256 : 0) + d] = v;
    }
}

// ---------------- elementwise: two products in one pass ----------------
__global__ void ew_mul2_kernel(const float* __restrict__ m,
                               const float* __restrict__ a, const float* __restrict__ b,
                               float* __restrict__ oa, float* __restrict__ ob)
{
    int i = blockIdx.x * 256 + threadIdx.x;
    float mv = m[i];
    oa[i] = mv * a[i];
    ob[i] = mv * b[i];
}

// ---------------- classifier ----------------
__global__ void __launch_bounds__(256) cls_kernel(
    const float* __restrict__ F, const float* __restrict__ W1,
    const float* __restrict__ W2, float* __restrict__ P)
{
    __shared__ float s_f[8][128];
    __shared__ float s_w1[32][129];
    __shared__ float s_w2[320];
    __shared__ float s_h[8][32];
    const int tid = threadIdx.x;
    const int r0 = blockIdx.x * 8;
    for (int idx = tid; idx < 1024; idx += 256) s_f[idx >> 7][idx & 127] = F[(size_t)r0 * 128 + idx];
    for (int idx = tid; idx < 4096; idx += 256) s_w1[idx >> 7][idx & 127] = W1[idx];
    for (int idx = tid; idx < 320; idx += 256) s_w2[idx] = W2[idx];
    __syncthreads();
    const int w = tid >> 5, lane = tid & 31;
    float h = 0.0f;
#pragma unroll 8
    for (int d = 0; d < 128; d++) h = fmaf(s_f[w][d], s_w1[lane][d], h);
    s_h[w][lane] = fmaxf(h, 0.0f);
    __syncwarp();
    if (lane < 10) {
        float p = 0.0f;
#pragma unroll
        for (int k = 0; k < 32; k++) p = fmaf(s_h[w][k], s_w2[lane * 32 + k], p);
        P[(size_t)(r0 + w) * 10 + lane] = p;
    }
}

// ---------------- host ----------------
static void launch_mma(const float* A, const float* W, const float* b, float* C,
                       int M, int N, int K, int flags,
                       const float* W2 = nullptr, int Ka = -1,
                       const float* E = nullptr, int eld = 0, int eoff = 0)
{
    if (Ka < 0) { Ka = K; W2 = W; }
    if (!E) E = A;
    dim3 grid(N / 64, M / 64);
    mma_gemm_kernel<<<grid, 128>>>(A, W, W2, b, C, M, N, K, Ka, flags, E, eld, eoff);
}

extern "C" void kernel_launch(void* const* d_in, const int* in_sizes, int n_in,
                              void* d_out, int out_size)
{
    const float* img    = (const float*)d_in[0];
    const float* audio  = (const float*)d_in[1];
    const float* vis_W  = (const float*)d_in[2];
    const float* vis_b  = (const float*)d_in[3];
    const float* aud_W  = (const float*)d_in[4];
    const float* aud_b  = (const float*)d_in[5];
    const float* msv_W  = (const float*)d_in[6];
    const float* msv_b  = (const float*)d_in[7];
    const float* msa_W  = (const float*)d_in[8];
    const float* msa_b  = (const float*)d_in[9];
    const float* mmfaW  = (const float*)d_in[10];
    const float* mmfaB  = (const float*)d_in[11];
    const float* bilW   = (const float*)d_in[12];
    const float* t_c    = (const float*)d_in[13];
    const float* out_W1 = (const float*)d_in[14];
    const float* out_b1 = (const float*)d_in[15];
    const float* out_W2 = (const float*)d_in[16];
    const float* out_b2 = (const float*)d_in[17];
    const float* clsvW1 = (const float*)d_in[18];
    const float* clsvW2 = (const float*)d_in[19];
    const float* clsaW1 = (const float*)d_in[20];
    const float* clsaW2 = (const float*)d_in[21];

    float* S = nullptr;
    cudaGetSymbolAddress((void**)&S, g_scratch);
    float* p_bf = nullptr;
    cudaGetSymbolAddress((void**)&p_bf, g_bias_fused);

    float* p_vis  = S;
    float* p_aud  = p_vis + N_BE;
    float* p_vms  = p_aud + N_BE;
    float* p_ams  = p_vms + N_BSD;
    float* p_qv   = p_ams + N_BSD;
    float* p_qa   = p_qv  + N_BSD;
    float* p_kv   = p_qa  + N_BSD;
    float* p_ka   = p_kv  + N_BSD;
    float* p_cat1 = p_ka  + N_BSD;        // [3072][512]
    float* p_cat2 = p_cat1 + 2 * N_BSD;   // [3072][512]
    float* p_cva  = p_cat2 + 2 * N_BSD;
    float* p_cav  = p_cva + N_BSD;
    float* p_bp   = p_cav + N_BSD;        // 4 x [3072][256]
    float* p_m    = p_bp  + 4 * N_BSD;
    float* p_xv   = p_m   + N_BSD;
    float* p_xa   = p_xv  + N_BSD;
    float* p_ov   = p_xa  + N_BSD;
    float* p_oa   = p_ov  + N_BSD;
    float* p_h    = p_oa  + N_BSD;

    const int nBlk = (int)(N_BSD / 256);

    cudaFuncSetAttribute(bilinear_f16_kernel,
                         cudaFuncAttributeMaxDynamicSharedMemorySize, BIL_SMEM_BYTES);

    // fused biases b4+b5 / b6+b7
    fuse_bias_kernel<<<1, 256>>>(mmfaB, p_bf);
    float* p_b45 = p_bf;
    float* p_b67 = p_bf + 256;

    auto run_mmfa = [&](const float* xv, const float* xa, float* outm) {
        launch_mma(xv, mmfaW + 0 * 65536, mmfaB + 0 * 256, p_qv, M3, Dd, Dd, 0);
        launch_mma(xa, mmfaW + 1 * 65536, mmfaB + 1 * 256, p_qa, M3, Dd, Dd, 0);
        launch_mma(xv, mmfaW + 2 * 65536, mmfaB + 2 * 256, p_kv, M3, Dd, Dd, 0);
        launch_mma(xa, mmfaW + 3 * 65536, mmfaB + 3 * 256, p_ka, M3, Dd, Dd, 0);
        attn_kernel<<<Bn, 256>>>(xv, xa, p_qv, p_qa, p_kv, p_ka, p_cat1, p_cat2);
        // c_va = sigm((lin4(ava)+lin5(av) + b4+b5) * av) : one K=512 GEMM, fused epilogue
        launch_mma(p_cat1, mmfaW + 4 * 65536, p_b45, p_cva, M3, Dd, 512, 4,
                   mmfaW + 5 * 65536, 256, p_cat1, 512, 256);
        launch_mma(p_cat2, mmfaW + 6 * 65536, p_b67, p_cav, M3, Dd, 512, 4,
                   mmfaW + 7 * 65536, 256, p_cat2, 512, 256);
        dim3 bg(48, 2, 4);
        bilinear_f16_kernel<<<bg, 256, BIL_SMEM_BYTES>>>(p_cva, p_cav, bilW, p_bp);
        bil_finish_kernel<<<nBlk, 256>>>(p_bp, xv, xa, t_c, outm);
    };

    // encoders + multi-scale (tf32 tensor path)
    launch_mma(img,   vis_W, vis_b, p_vis, Bn, 1024, 4096, 1);
    launch_mma(audio, aud_W, aud_b, p_aud, Bn, 1024, 1024, 1);
    launch_mma(p_vis, msv_W, msv_b, p_vms, Bn, SD, 1024, 1);
    launch_mma(p_aud, msa_W, msa_b, p_ams, Bn, SD, 1024, 1);

    run_mmfa(p_vms, p_ams, p_m);
    ew_mul2_kernel<<<nBlk, 256>>>(p_m, p_vms, p_ams, p_xv, p_xa);

    run_mmfa(p_xv, p_xa, p_m);
    ew_mul2_kernel<<<nBlk, 256>>>(p_m, p_vms, p_ams, p_ov, p_oa);

    float* out = (float*)d_out;
    float* fv = out;
    float* fa = out + (size_t)Bn * LAT;
    float* pv = fa + (size_t)Bn * LAT;
    float* pa = pv + (size_t)Bn * 10;

    launch_mma(p_ov, out_W1, out_b1, p_h, Bn, OUT1, SD, 1);
    launch_mma(p_h,  out_W2, out_b2, fv,  Bn, LAT, OUT1, 0);
    launch_mma(p_oa, out_W1, out_b1, p_h, Bn, OUT1, SD, 1);
    launch_mma(p_h,  out_W2, out_b2, fa,  Bn, LAT, OUT1, 0);

    cls_kernel<<<Bn / 8, 256>>>(fv, clsvW1, clsvW2, pv);
    cls_kernel<<<Bn / 8, 256>>>(fa, clsaW1, clsaW2, pa);
}